// round 4
// baseline (speedup 1.0000x reference)
#include <cuda_runtime.h>

#define NB 64
#define NS 256
#define NI 256
#define NHH 512
#define N2H 1024
#define NM (NB*NS)

// Scratch for the pre-activation GEMM output i = x @ W^T   [16384 x 1024], 64MB
static __device__ float g_C[(size_t)NM * N2H];

typedef unsigned long long u64;
__device__ __forceinline__ u64 pk2(float lo, float hi){ u64 r; asm("mov.b64 %0,{%1,%2};" : "=l"(r) : "f"(lo), "f"(hi)); return r; }
__device__ __forceinline__ void up2(u64 a, float& lo, float& hi){ asm("mov.b64 {%0,%1},%2;" : "=f"(lo), "=f"(hi) : "l"(a)); }
__device__ __forceinline__ u64 fma2(u64 a, u64 b, u64 c){ u64 d; asm("fma.rn.f32x2 %0,%1,%2,%3;" : "=l"(d) : "l"(a), "l"(b), "l"(c)); return d; }
__device__ __forceinline__ u64 mul2(u64 a, u64 b){ u64 d; asm("mul.rn.f32x2 %0,%1,%2;" : "=l"(d) : "l"(a), "l"(b)); return d; }
__device__ __forceinline__ u64 add2(u64 a, u64 b){ u64 d; asm("add.rn.f32x2 %0,%1,%2;" : "=l"(d) : "l"(a), "l"(b)); return d; }

// Exact-ish tanh for the trace kernel (rel err ~1e-6).
__device__ __forceinline__ float fast_tanh(float x){
    float z = __expf(2.0f * x);
    return 1.0f - __fdividef(2.0f, z + 1.0f);
}
// Single-instruction MUFU.TANH (sm_75+), rel err ~1.6e-5.
__device__ __forceinline__ float tanh_approx(float x){
    float r; asm("tanh.approx.f32 %0, %1;" : "=f"(r) : "f"(x)); return r;
}

union F4U { float4 f; u64 u[2]; };

// ---------------------------------------------------------------------------
// Kernel 1: SGEMM  C[m][n] = sum_k x[m][k] * W[n][k]
// M=16384, N=1024, K=256.  128x128 tile, BK=32, 256 threads, 8x8 per thread.
// Register-staged pipeline (LDG next tile while computing current).
// Padding +4 keeps rows float4-aligned (stride 132) — REQUIRED for the
// vectorized smem reads below.
// ---------------------------------------------------------------------------
#define BM 128
#define BN 128
#define BK 32

__global__ __launch_bounds__(256) void sgemm_kernel(const float* __restrict__ A,
                                                    const float* __restrict__ W)
{
    __shared__ float As[BK][BM+4];
    __shared__ float Bs[BK][BN+4];
    const int tid = threadIdx.x;
    const int m0 = blockIdx.y * BM;
    const int n0 = blockIdx.x * BN;
    const int tr = tid >> 4;        // 0..15
    const int tc = tid & 15;        // 0..15

    float acc[8][8];
    #pragma unroll
    for (int i=0;i<8;i++)
        #pragma unroll
        for (int j=0;j<8;j++) acc[i][j]=0.f;

    const int lr = tid >> 3;          // 0..31
    const int lc = (tid & 7) << 2;    // 0,4,...,28

    float4 an[4], bn[4];
    // preload tile 0
    #pragma unroll
    for (int h=0; h<4; h++){
        int r = lr + h*32;
        an[h] = *(const float4*)(A + (size_t)(m0+r)*NI + lc);
        bn[h] = *(const float4*)(W + (size_t)(n0+r)*NI + lc);
    }

    #pragma unroll
    for (int k0=0; k0<NI; k0+=BK){
        // commit staged tile to smem
        #pragma unroll
        for (int h=0; h<4; h++){
            int r = lr + h*32;
            As[lc+0][r]=an[h].x; As[lc+1][r]=an[h].y; As[lc+2][r]=an[h].z; As[lc+3][r]=an[h].w;
            Bs[lc+0][r]=bn[h].x; Bs[lc+1][r]=bn[h].y; Bs[lc+2][r]=bn[h].z; Bs[lc+3][r]=bn[h].w;
        }
        __syncthreads();
        // stage next tile (overlaps with FFMA below)
        if (k0 + BK < NI){
            #pragma unroll
            for (int h=0; h<4; h++){
                int r = lr + h*32;
                an[h] = *(const float4*)(A + (size_t)(m0+r)*NI + k0 + BK + lc);
                bn[h] = *(const float4*)(W + (size_t)(n0+r)*NI + k0 + BK + lc);
            }
        }
        #pragma unroll
        for (int kk=0;kk<BK;kk++){
            float a[8], bb[8];
            *(float4*)(a)    = *(const float4*)(&As[kk][tr*8]);
            *(float4*)(a+4)  = *(const float4*)(&As[kk][tr*8+4]);
            *(float4*)(bb)   = *(const float4*)(&Bs[kk][tc*8]);
            *(float4*)(bb+4) = *(const float4*)(&Bs[kk][tc*8+4]);
            #pragma unroll
            for (int i=0;i<8;i++)
                #pragma unroll
                for (int j=0;j<8;j++)
                    acc[i][j] = fmaf(a[i], bb[j], acc[i][j]);
        }
        __syncthreads();
    }
    #pragma unroll
    for (int i=0;i<8;i++){
        float* cptr = g_C + (size_t)(m0 + tr*8 + i)*N2H + n0 + tc*8;
        *(float4*)(cptr)   = make_float4(acc[i][0],acc[i][1],acc[i][2],acc[i][3]);
        *(float4*)(cptr+4) = make_float4(acc[i][4],acc[i][5],acc[i][6],acc[i][7]);
    }
}

// ---------------------------------------------------------------------------
// Kernel 2: k-trace precompute. Per (b,h): ks recurrence + tanh -> keys output.
// ---------------------------------------------------------------------------
__global__ __launch_bounds__(256) void trace_kernel(float* __restrict__ keys_out)
{
    int gid = blockIdx.x*blockDim.x + threadIdx.x;   // 0..32767
    int b = gid >> 9;
    int h = gid & 511;
    const float* c = g_C + (size_t)b*NS*N2H + h;      // ik column
    float* ko = keys_out + (size_t)b*NS*NHH + h;
    const float ALPHA = 0.9048374180359595f;
    float ks = 0.f;
    #pragma unroll 8
    for (int t=0;t<NS;t++){
        ks = fmaf(ks, ALPHA, __ldg(c + (size_t)t*N2H));
        ko[(size_t)t*NHH] = fast_tanh(ks);
    }
}

// ---------------------------------------------------------------------------
// Kernel 3: main recurrence. One warp owns 4 mem rows (scaled: m'' = mem/P).
// Scalar chain fully packed in f32x2; tanh via MUFU.TANH.
// Grid: (32 row-groups, 64 batches) x 128 threads (4 warps x 4 rows = 16 rows).
// ---------------------------------------------------------------------------
__global__ __launch_bounds__(128, 3) void recur_kernel(const float* __restrict__ keys,
                                                       float* __restrict__ mem_out,
                                                       float* __restrict__ vals_out)
{
    const int b    = blockIdx.y;
    const int rg   = blockIdx.x;       // 0..31
    const int warp = threadIdx.x >> 5; // 0..3
    const int lane = threadIdx.x & 31;
    const int row0 = rg*16 + warp*4;

    const float ALPHA = 0.9048374180359595f;   // exp(-1/10)
    const float DEC   = 0.9512294245007140f;   // exp(-1/20)
    const float OMD   = 0.0487705754992860f;   // 1 - DEC
    const float LR    = 0.01f;

    u64 m[4][8], kt[8];
    #pragma unroll
    for (int r=0;r<4;r++)
        #pragma unroll
        for (int p=0;p<8;p++) m[r][p]=0ULL;
    #pragma unroll
    for (int p=0;p<8;p++) kt[p]=0ULL;

    // packed per-row scalar state: (row0,row1) and (row2,row3)
    u64 vs01=0ULL, vs23=0ULL, vt01=0ULL, vt23=0ULL;
    u64 P01 = pk2(1.f,1.f),        P23 = pk2(1.f,1.f);
    u64 Q01 = pk2(LR*OMD, LR*OMD), Q23 = Q01;

    const u64 ONE2   = pk2(1.f, 1.f);
    const u64 NEG2   = pk2(-1.f, -1.f);
    const u64 A2     = pk2(ALPHA, ALPHA);
    const u64 DEC2   = pk2(DEC, DEC);
    const u64 OMD2   = pk2(OMD, OMD);
    const u64 LR2    = pk2(LR, LR);
    const u64 K02    = pk2(0.2f, 0.2f);

    const float4* kb  = (const float4*)(keys + (size_t)b*NS*NHH) + lane;
    const float4* ivb = (const float4*)(g_C + (size_t)b*NS*N2H + NHH + row0);
    float4*       vb  = (float4*)(vals_out + (size_t)b*NS*NHH + row0);

    // prefetch t=0
    float4 kf[4];
    #pragma unroll
    for (int c=0;c<4;c++) kf[c] = __ldg(&kb[c*32]);
    float4 ivf = __ldg(&ivb[0]);

    for (int t=0;t<NS;t++){
        // commit prefetched k, iv
        u64 kp[8];
        #pragma unroll
        for (int c=0;c<4;c++){
            F4U kv; kv.f = kf[c];
            kp[2*c] = kv.u[0]; kp[2*c+1] = kv.u[1];
        }
        u64 iv01 = pk2(ivf.x, ivf.y);
        u64 iv23 = pk2(ivf.z, ivf.w);

        // prefetch next step (clamped)
        int tn = (t+1 < NS) ? (t+1) : t;
        #pragma unroll
        for (int c=0;c<4;c++) kf[c] = __ldg(&kb[(size_t)tn*(NHH/4) + c*32]);
        ivf = __ldg(&ivb[(size_t)tn*(N2H/4)]);

        // dots with current (scaled) mem
        u64 a[4];
        #pragma unroll
        for (int r=0;r<4;r++){
            u64 acc = 0ULL;
            #pragma unroll
            for (int p=0;p<8;p++) acc = fma2(m[r][p], kp[p], acc);
            a[r] = acc;
        }

        // kt' update (independent of reduce -> overlaps shfl latency)
        #pragma unroll
        for (int p=0;p<8;p++) kt[p] = fma2(kt[p], DEC2, kp[p]);

        // horizontal + butterfly allreduce (two packed chains in parallel)
        float x,y;
        up2(a[0],x,y); float h0 = x+y;
        up2(a[1],x,y); float h1 = x+y;
        up2(a[2],x,y); float h2 = x+y;
        up2(a[3],x,y); float h3 = x+y;
        u64 r01 = pk2(h0,h1), r23 = pk2(h2,h3);
        #pragma unroll
        for (int o=16;o;o>>=1){
            r01 = add2(r01, __shfl_xor_sync(0xffffffffu, r01, o));
            r23 = add2(r23, __shfl_xor_sync(0xffffffffu, r23, o));
        }

        // packed scalar chains (warp-uniform, replicated across lanes)
        u64 d01 = mul2(r01, P01);
        u64 d23 = mul2(r23, P23);
        vs01 = fma2(vs01, A2, fma2(K02, d01, iv01));
        vs23 = fma2(vs23, A2, fma2(K02, d23, iv23));
        float v0,v1,v2,v3;
        { float s0,s1; up2(vs01,s0,s1); v0=tanh_approx(s0); v1=tanh_approx(s1); }
        { float s2,s3; up2(vs23,s2,s3); v2=tanh_approx(s2); v3=tanh_approx(s3); }
        u64 v01 = pk2(v0,v1), v23 = pk2(v2,v3);
        vt01 = fma2(v01, OMD2, mul2(vt01, DEC2));
        vt23 = fma2(v23, OMD2, mul2(vt23, DEC2));
        u64 e01 = mul2(mul2(vt01, vt01), LR2);
        u64 e23 = mul2(mul2(vt23, vt23), LR2);
        u64 c101 = fma2(e01, NEG2, ONE2);               // 1 - e
        u64 c123 = fma2(e23, NEG2, ONE2);
        P01 = mul2(P01, c101);
        P23 = mul2(P23, c123);
        // 1/(1-e) ~= 1 + e + e^2 + e^3  (err ~ e^4 <= 1e-8)
        u64 inv01 = fma2(e01, fma2(e01, add2(ONE2, e01), ONE2), ONE2);
        u64 inv23 = fma2(e23, fma2(e23, add2(ONE2, e23), ONE2), ONE2);
        Q01 = mul2(Q01, inv01);
        Q23 = mul2(Q23, inv23);
        u64 w01 = mul2(Q01, vt01);
        u64 w23 = mul2(Q23, vt23);

        if (lane == 0)
            vb[(size_t)t*(NHH/4)] = make_float4(v0, v1, v2, v3);

        // scaled mem update: m''_r += kt' * w_r   (1 fma2 per element-pair)
        float w0,w1,w2,w3;
        up2(w01,w0,w1); up2(w23,w2,w3);
        u64 wp0=pk2(w0,w0), wp1=pk2(w1,w1), wp2=pk2(w2,w2), wp3=pk2(w3,w3);
        #pragma unroll
        for (int p=0;p<8;p++){
            m[0][p] = fma2(kt[p], wp0, m[0][p]);
            m[1][p] = fma2(kt[p], wp1, m[1][p]);
            m[2][p] = fma2(kt[p], wp2, m[2][p]);
            m[3][p] = fma2(kt[p], wp3, m[3][p]);
        }
    }

    // write final mem rows: mem = P_r * m''_r
    float Pf[4];
    up2(P01, Pf[0], Pf[1]); up2(P23, Pf[2], Pf[3]);
    #pragma unroll
    for (int r=0;r<4;r++){
        u64 Pp = pk2(Pf[r], Pf[r]);
        float* mo = mem_out + ((size_t)b*NHH + row0 + r)*NHH + lane*4;
        #pragma unroll
        for (int c=0;c<4;c++){
            F4U u;
            u.u[0] = mul2(m[r][2*c],   Pp);
            u.u[1] = mul2(m[r][2*c+1], Pp);
            *(float4*)(mo + c*128) = u.f;
        }
    }
}

// ---------------------------------------------------------------------------
extern "C" void kernel_launch(void* const* d_in, const int* in_sizes, int n_in,
                              void* d_out, int out_size)
{
    const float* x = (const float*)d_in[0];   // [64,256,256]
    const float* W = (const float*)d_in[1];   // [1024,256]
    float* out = (float*)d_out;
    float* mem_out  = out;                                    // [64,512,512]
    float* keys_out = out + (size_t)NB*NHH*NHH;               // [64,256,512]
    float* vals_out = keys_out + (size_t)NB*NS*NHH;           // [64,256,512]

    dim3 g1(N2H/BN, NM/BM);                 // (8, 128)
    sgemm_kernel<<<g1, 256>>>(x, W);
    trace_kernel<<<(NB*NHH)/256, 256>>>(keys_out);
    recur_kernel<<<dim3(32, NB), 128>>>(keys_out, mem_out, vals_out);
}

// round 5
// speedup vs baseline: 1.2677x; 1.2677x over previous
#include <cuda_runtime.h>

#define NB 64
#define NS 256
#define NI 256
#define NHH 512
#define N2H 1024
#define NM (NB*NS)

// Scratch for the pre-activation GEMM output i = x @ W^T   [16384 x 1024], 64MB
static __device__ float g_C[(size_t)NM * N2H];

typedef unsigned long long u64;
__device__ __forceinline__ u64 pk2(float lo, float hi){ u64 r; asm("mov.b64 %0,{%1,%2};" : "=l"(r) : "f"(lo), "f"(hi)); return r; }
__device__ __forceinline__ void up2(u64 a, float& lo, float& hi){ asm("mov.b64 {%0,%1},%2;" : "=f"(lo), "=f"(hi) : "l"(a)); }
__device__ __forceinline__ u64 fma2(u64 a, u64 b, u64 c){ u64 d; asm("fma.rn.f32x2 %0,%1,%2,%3;" : "=l"(d) : "l"(a), "l"(b), "l"(c)); return d; }
__device__ __forceinline__ u64 mul2(u64 a, u64 b){ u64 d; asm("mul.rn.f32x2 %0,%1,%2;" : "=l"(d) : "l"(a), "l"(b)); return d; }
__device__ __forceinline__ u64 add2(u64 a, u64 b){ u64 d; asm("add.rn.f32x2 %0,%1,%2;" : "=l"(d) : "l"(a), "l"(b)); return d; }

// Exact-ish tanh for the trace kernel (rel err ~1e-6).
__device__ __forceinline__ float fast_tanh(float x){
    float z = __expf(2.0f * x);
    return 1.0f - __fdividef(2.0f, z + 1.0f);
}
// Single-instruction MUFU.TANH (sm_75+), rel err ~1.6e-5.
__device__ __forceinline__ float tanh_approx(float x){
    float r; asm("tanh.approx.f32 %0, %1;" : "=f"(r) : "f"(x)); return r;
}

union F4U { float4 f; u64 u[2]; };

// ---------------------------------------------------------------------------
// Kernel 1: SGEMM  C[m][n] = sum_k x[m][k] * W[n][k]
// EXACT R2 version (201us measured): 128x128 tile, BK=32, 256 thd, 8x8/thread,
// 127 regs -> 2 blocks/SM. Do NOT register-stage (regs>128 halves occupancy).
// ---------------------------------------------------------------------------
#define BM 128
#define BN 128
#define BK 32

__global__ __launch_bounds__(256) void sgemm_kernel(const float* __restrict__ A,
                                                    const float* __restrict__ W)
{
    __shared__ float As[BK][BM+4];
    __shared__ float Bs[BK][BN+4];
    const int tid = threadIdx.x;
    const int m0 = blockIdx.y * BM;
    const int n0 = blockIdx.x * BN;
    const int tr = tid >> 4;        // 0..15
    const int tc = tid & 15;        // 0..15

    float acc[8][8];
    #pragma unroll
    for (int i=0;i<8;i++)
        #pragma unroll
        for (int j=0;j<8;j++) acc[i][j]=0.f;

    const int lr = tid >> 3;          // 0..31
    const int lc = (tid & 7) << 2;    // 0,4,...,28

    for (int k0=0; k0<NI; k0+=BK){
        #pragma unroll
        for (int h=0; h<4; h++){
            int r = lr + h*32;
            float4 av = *(const float4*)(A + (size_t)(m0+r)*NI + k0 + lc);
            As[lc+0][r]=av.x; As[lc+1][r]=av.y; As[lc+2][r]=av.z; As[lc+3][r]=av.w;
            float4 bv = *(const float4*)(W + (size_t)(n0+r)*NI + k0 + lc);
            Bs[lc+0][r]=bv.x; Bs[lc+1][r]=bv.y; Bs[lc+2][r]=bv.z; Bs[lc+3][r]=bv.w;
        }
        __syncthreads();
        #pragma unroll
        for (int kk=0;kk<BK;kk++){
            float a[8], bb[8];
            *(float4*)(a)    = *(const float4*)(&As[kk][tr*8]);
            *(float4*)(a+4)  = *(const float4*)(&As[kk][tr*8+4]);
            *(float4*)(bb)   = *(const float4*)(&Bs[kk][tc*8]);
            *(float4*)(bb+4) = *(const float4*)(&Bs[kk][tc*8+4]);
            #pragma unroll
            for (int i=0;i<8;i++)
                #pragma unroll
                for (int j=0;j<8;j++)
                    acc[i][j] = fmaf(a[i], bb[j], acc[i][j]);
        }
        __syncthreads();
    }
    #pragma unroll
    for (int i=0;i<8;i++){
        float* cptr = g_C + (size_t)(m0 + tr*8 + i)*N2H + n0 + tc*8;
        *(float4*)(cptr)   = make_float4(acc[i][0],acc[i][1],acc[i][2],acc[i][3]);
        *(float4*)(cptr+4) = make_float4(acc[i][4],acc[i][5],acc[i][6],acc[i][7]);
    }
}

// ---------------------------------------------------------------------------
// Kernel 2: k-trace precompute.
// ---------------------------------------------------------------------------
__global__ __launch_bounds__(256) void trace_kernel(float* __restrict__ keys_out)
{
    int gid = blockIdx.x*blockDim.x + threadIdx.x;   // 0..32767
    int b = gid >> 9;
    int h = gid & 511;
    const float* c = g_C + (size_t)b*NS*N2H + h;      // ik column
    float* ko = keys_out + (size_t)b*NS*NHH + h;
    const float ALPHA = 0.9048374180359595f;
    float ks = 0.f;
    #pragma unroll 8
    for (int t=0;t<NS;t++){
        ks = fmaf(ks, ALPHA, __ldg(c + (size_t)t*N2H));
        ko[(size_t)t*NHH] = fast_tanh(ks);
    }
}

// ---------------------------------------------------------------------------
// Kernel 3: main recurrence with ONE-STEP LOOKAHEAD.
//   dot_t = pd_t + w_{t-1} * gk_t,   pd_t = m''_{t-2}.k_t,  gk_t = kt'_{t-1}.k_t
// pd/gk for step t+1 are computed at the END of step t (dots + reduce have a
// full iteration of slack), so the loop-carried path is just the scalar chain.
// One warp owns 4 scaled mem rows (m'' = mem/P) in registers.
// ---------------------------------------------------------------------------
__global__ __launch_bounds__(128, 3) void recur_kernel(const float* __restrict__ keys,
                                                       float* __restrict__ mem_out,
                                                       float* __restrict__ vals_out)
{
    const int b    = blockIdx.y;
    const int rg   = blockIdx.x;       // 0..31
    const int warp = threadIdx.x >> 5; // 0..3
    const int lane = threadIdx.x & 31;
    const int row0 = rg*16 + warp*4;

    const float ALPHA = 0.9048374180359595f;   // exp(-1/10)
    const float DEC   = 0.9512294245007140f;   // exp(-1/20)
    const float OMD   = 0.0487705754992860f;   // 1 - DEC
    const float LR    = 0.01f;

    u64 m[4][8], kt[8], kc[8];
    #pragma unroll
    for (int r=0;r<4;r++)
        #pragma unroll
        for (int p=0;p<8;p++) m[r][p]=0ULL;
    #pragma unroll
    for (int p=0;p<8;p++){ kt[p]=0ULL; kc[p]=0ULL; }

    // packed per-row scalar state
    u64 vs01=0ULL, vs23=0ULL, vt01=0ULL, vt23=0ULL;
    u64 P01 = pk2(1.f,1.f),        P23 = pk2(1.f,1.f);
    u64 Q01 = pk2(LR*OMD, LR*OMD), Q23 = Q01;
    u64 pd01 = 0ULL, pd23 = 0ULL;      // lookahead raw dots m''.k_t
    float gk = 0.f;                    // kt'.k_t
    u64 w01p = 0ULL, w23p = 0ULL;      // w''_{t-1} packed

    const u64 ONE2   = pk2(1.f, 1.f);
    const u64 NEG2   = pk2(-1.f, -1.f);
    const u64 A2     = pk2(ALPHA, ALPHA);
    const u64 DEC2   = pk2(DEC, DEC);
    const u64 OMD2   = pk2(OMD, OMD);
    const u64 LR2    = pk2(LR, LR);
    const u64 K02    = pk2(0.2f, 0.2f);

    const float4* kb  = (const float4*)(keys + (size_t)b*NS*NHH) + lane;
    const float4* ivb = (const float4*)(g_C + (size_t)b*NS*N2H + NHH + row0);
    float4*       vb  = (float4*)(vals_out + (size_t)b*NS*NHH + row0);

    // preload k_0 into kc (as "k_t" for iter 0), prefetch k_1 and iv_0
    {
        #pragma unroll
        for (int c=0;c<4;c++){
            F4U kv; kv.f = __ldg(&kb[c*32]);
            kc[2*c]=kv.u[0]; kc[2*c+1]=kv.u[1];
        }
    }
    float4 kf[4];
    #pragma unroll
    for (int c=0;c<4;c++) kf[c] = __ldg(&kb[(size_t)1*(NHH/4) + c*32]);
    float4 ivf = __ldg(&ivb[0]);

    for (int t=0;t<NS;t++){
        // issue loads for next iteration early
        float4 ivn = __ldg(&ivb[(size_t)((t+1<NS)?(t+1):t)*(N2H/4)]);

        u64 iv01 = pk2(ivf.x, ivf.y);
        u64 iv23 = pk2(ivf.z, ivf.w);

        // ---- (1)(2) true dot via lookahead + packed scalar chain ----
        u64 gk2   = pk2(gk, gk);
        u64 dot01 = fma2(w01p, gk2, pd01);     // m''_{t-1}.k_t
        u64 dot23 = fma2(w23p, gk2, pd23);
        u64 d01 = mul2(dot01, P01);            // unscale: P_{t-1} * raw
        u64 d23 = mul2(dot23, P23);
        vs01 = fma2(vs01, A2, fma2(K02, d01, iv01));
        vs23 = fma2(vs23, A2, fma2(K02, d23, iv23));
        float v0,v1,v2,v3;
        { float s0,s1; up2(vs01,s0,s1); v0=tanh_approx(s0); v1=tanh_approx(s1); }
        { float s2,s3; up2(vs23,s2,s3); v2=tanh_approx(s2); v3=tanh_approx(s3); }
        u64 v01 = pk2(v0,v1), v23 = pk2(v2,v3);
        vt01 = fma2(v01, OMD2, mul2(vt01, DEC2));
        vt23 = fma2(v23, OMD2, mul2(vt23, DEC2));
        u64 e01 = mul2(mul2(vt01, vt01), LR2);
        u64 e23 = mul2(mul2(vt23, vt23), LR2);
        P01 = mul2(P01, fma2(e01, NEG2, ONE2));
        P23 = mul2(P23, fma2(e23, NEG2, ONE2));
        // 1/(1-e) ~= 1+e+e^2+e^3
        Q01 = mul2(Q01, fma2(e01, fma2(e01, add2(ONE2, e01), ONE2), ONE2));
        Q23 = mul2(Q23, fma2(e23, fma2(e23, add2(ONE2, e23), ONE2), ONE2));
        u64 w01 = mul2(Q01, vt01);             // w''_t
        u64 w23 = mul2(Q23, vt23);

        if (lane == 0)
            vb[(size_t)t*(NHH/4)] = make_float4(v0, v1, v2, v3);

        // ---- (3) apply PREVIOUS rank-1 update: m'' += kt'_{t-1} * w''_{t-1} ----
        {
            float a0,a1,a2,a3;
            up2(w01p,a0,a1); up2(w23p,a2,a3);
            u64 wp0=pk2(a0,a0), wp1=pk2(a1,a1), wp2=pk2(a2,a2), wp3=pk2(a3,a3);
            #pragma unroll
            for (int p=0;p<8;p++){
                m[0][p] = fma2(kt[p], wp0, m[0][p]);
                m[1][p] = fma2(kt[p], wp1, m[1][p]);
                m[2][p] = fma2(kt[p], wp2, m[2][p]);
                m[3][p] = fma2(kt[p], wp3, m[3][p]);
            }
        }

        // ---- (4) kt' update with k_t ----
        #pragma unroll
        for (int p=0;p<8;p++) kt[p] = fma2(kt[p], DEC2, kc[p]);

        // ---- (5) commit k_{t+1}; prefetch k_{t+2} ----
        #pragma unroll
        for (int c=0;c<4;c++){
            F4U kv; kv.f = kf[c];
            kc[2*c]=kv.u[0]; kc[2*c+1]=kv.u[1];
        }
        int tnn = (t+2 < NS) ? (t+2) : (NS-1);
        #pragma unroll
        for (int c=0;c<4;c++) kf[c] = __ldg(&kb[(size_t)tnn*(NHH/4) + c*32]);

        // ---- (6) lookahead dots against k_{t+1} (two trees) + reduce ----
        u64 a[4], g0=0ULL, g1=0ULL;
        #pragma unroll
        for (int r=0;r<4;r++){
            u64 s0=0ULL, s1=0ULL;
            #pragma unroll
            for (int p=0;p<8;p+=2){
                s0 = fma2(m[r][p],   kc[p],   s0);
                s1 = fma2(m[r][p+1], kc[p+1], s1);
            }
            a[r] = add2(s0, s1);
        }
        #pragma unroll
        for (int p=0;p<8;p+=2){
            g0 = fma2(kt[p],   kc[p],   g0);
            g1 = fma2(kt[p+1], kc[p+1], g1);
        }
        u64 ag = add2(g0, g1);
        float x,y;
        up2(a[0],x,y); float h0 = x+y;
        up2(a[1],x,y); float h1 = x+y;
        up2(a[2],x,y); float h2 = x+y;
        up2(a[3],x,y); float h3 = x+y;
        up2(ag,  x,y); float hg = x+y;
        u64 r01 = pk2(h0,h1), r23 = pk2(h2,h3), rg = pk2(hg,hg);
        #pragma unroll
        for (int o=16;o;o>>=1){
            r01 = add2(r01, __shfl_xor_sync(0xffffffffu, r01, o));
            r23 = add2(r23, __shfl_xor_sync(0xffffffffu, r23, o));
            rg  = add2(rg,  __shfl_xor_sync(0xffffffffu, rg,  o));
        }
        pd01 = r01; pd23 = r23;
        { float glo, ghi; up2(rg, glo, ghi); gk = glo; }

        // ---- (7) rotate ----
        w01p = w01; w23p = w23;
        ivf = ivn;
    }

    // final pending rank-1 update: m'' += kt'_{NS-1} * w''_{NS-1}
    {
        float a0,a1,a2,a3;
        up2(w01p,a0,a1); up2(w23p,a2,a3);
        u64 wp0=pk2(a0,a0), wp1=pk2(a1,a1), wp2=pk2(a2,a2), wp3=pk2(a3,a3);
        #pragma unroll
        for (int p=0;p<8;p++){
            m[0][p] = fma2(kt[p], wp0, m[0][p]);
            m[1][p] = fma2(kt[p], wp1, m[1][p]);
            m[2][p] = fma2(kt[p], wp2, m[2][p]);
            m[3][p] = fma2(kt[p], wp3, m[3][p]);
        }
    }

    // write final mem rows: mem = P_r * m''_r
    float Pf[4];
    up2(P01, Pf[0], Pf[1]); up2(P23, Pf[2], Pf[3]);
    #pragma unroll
    for (int r=0;r<4;r++){
        u64 Pp = pk2(Pf[r], Pf[r]);
        float* mo = mem_out + ((size_t)b*NHH + row0 + r)*NHH + lane*4;
        #pragma unroll
        for (int c=0;c<4;c++){
            F4U u;
            u.u[0] = mul2(m[r][2*c],   Pp);
            u.u[1] = mul2(m[r][2*c+1], Pp);
            *(float4*)(mo + c*128) = u.f;
        }
    }
}

// ---------------------------------------------------------------------------
extern "C" void kernel_launch(void* const* d_in, const int* in_sizes, int n_in,
                              void* d_out, int out_size)
{
    const float* x = (const float*)d_in[0];   // [64,256,256]
    const float* W = (const float*)d_in[1];   // [1024,256]
    float* out = (float*)d_out;
    float* mem_out  = out;                                    // [64,512,512]
    float* keys_out = out + (size_t)NB*NHH*NHH;               // [64,256,512]
    float* vals_out = keys_out + (size_t)NB*NS*NHH;           // [64,256,512]

    dim3 g1(N2H/BN, NM/BM);                 // (8, 128)
    sgemm_kernel<<<g1, 256>>>(x, W);
    trace_kernel<<<(NB*NHH)/256, 256>>>(keys_out);
    recur_kernel<<<dim3(32, NB), 128>>>(keys_out, mem_out, vals_out);
}

// round 6
// speedup vs baseline: 1.3838x; 1.0916x over previous
#include <cuda_runtime.h>

#define NB 64
#define NS 256
#define NI 256
#define NHH 512
#define N2H 1024
#define NM (NB*NS)

// Scratch for the pre-activation GEMM output i = x @ W^T   [16384 x 1024], 64MB
static __device__ float g_C[(size_t)NM * N2H];

typedef unsigned long long u64;
__device__ __forceinline__ u64 pk2(float lo, float hi){ u64 r; asm("mov.b64 %0,{%1,%2};" : "=l"(r) : "f"(lo), "f"(hi)); return r; }
__device__ __forceinline__ void up2(u64 a, float& lo, float& hi){ asm("mov.b64 {%0,%1},%2;" : "=f"(lo), "=f"(hi) : "l"(a)); }
__device__ __forceinline__ u64 fma2(u64 a, u64 b, u64 c){ u64 d; asm("fma.rn.f32x2 %0,%1,%2,%3;" : "=l"(d) : "l"(a), "l"(b), "l"(c)); return d; }
__device__ __forceinline__ u64 mul2(u64 a, u64 b){ u64 d; asm("mul.rn.f32x2 %0,%1,%2;" : "=l"(d) : "l"(a), "l"(b)); return d; }
__device__ __forceinline__ u64 add2(u64 a, u64 b){ u64 d; asm("add.rn.f32x2 %0,%1,%2;" : "=l"(d) : "l"(a), "l"(b)); return d; }

// Exact-ish tanh for the trace kernel (rel err ~1e-6).
__device__ __forceinline__ float fast_tanh(float x){
    float z = __expf(2.0f * x);
    return 1.0f - __fdividef(2.0f, z + 1.0f);
}
// Single-instruction MUFU.TANH (sm_75+), rel err ~1.6e-5.
__device__ __forceinline__ float tanh_approx(float x){
    float r; asm("tanh.approx.f32 %0, %1;" : "=f"(r) : "f"(x)); return r;
}

union F4U { float4 f; u64 u[2]; };

// ---------------------------------------------------------------------------
// Kernel 1: SGEMM  C[m][n] = sum_k x[m][k] * W[n][k]
// 128x128 tile, BK=32, 256 thd, 8x8 per thread, inner loop in fma.rn.f32x2
// (2x fp32 rate vs scalar FFMA; ptxas never emits FFMA2 from C++).
// ---------------------------------------------------------------------------
#define BM 128
#define BN 128
#define BK 32

__global__ __launch_bounds__(256) void sgemm_kernel(const float* __restrict__ A,
                                                    const float* __restrict__ W)
{
    __shared__ float As[BK][BM+4];
    __shared__ float Bs[BK][BN+4];
    const int tid = threadIdx.x;
    const int m0 = blockIdx.y * BM;
    const int n0 = blockIdx.x * BN;
    const int tr = tid >> 4;        // 0..15
    const int tc = tid & 15;        // 0..15

    u64 acc2[8][4];                 // [i][j-pair], 8 rows x 8 cols packed
    #pragma unroll
    for (int i=0;i<8;i++)
        #pragma unroll
        for (int j=0;j<4;j++) acc2[i][j]=0ULL;

    const int lr = tid >> 3;          // 0..31
    const int lc = (tid & 7) << 2;    // 0,4,...,28

    for (int k0=0; k0<NI; k0+=BK){
        #pragma unroll
        for (int h=0; h<4; h++){
            int r = lr + h*32;
            float4 av = *(const float4*)(A + (size_t)(m0+r)*NI + k0 + lc);
            As[lc+0][r]=av.x; As[lc+1][r]=av.y; As[lc+2][r]=av.z; As[lc+3][r]=av.w;
            float4 bv = *(const float4*)(W + (size_t)(n0+r)*NI + k0 + lc);
            Bs[lc+0][r]=bv.x; Bs[lc+1][r]=bv.y; Bs[lc+2][r]=bv.z; Bs[lc+3][r]=bv.w;
        }
        __syncthreads();
        #pragma unroll
        for (int kk=0;kk<BK;kk++){
            float a[8];
            u64 bb2[4];
            *(float4*)(a)    = *(const float4*)(&As[kk][tr*8]);
            *(float4*)(a+4)  = *(const float4*)(&As[kk][tr*8+4]);
            { F4U b; b.f = *(const float4*)(&Bs[kk][tc*8]);   bb2[0]=b.u[0]; bb2[1]=b.u[1]; }
            { F4U b; b.f = *(const float4*)(&Bs[kk][tc*8+4]); bb2[2]=b.u[0]; bb2[3]=b.u[1]; }
            #pragma unroll
            for (int i=0;i<8;i++){
                u64 a2 = pk2(a[i], a[i]);
                #pragma unroll
                for (int j=0;j<4;j++)
                    acc2[i][j] = fma2(a2, bb2[j], acc2[i][j]);
            }
        }
        __syncthreads();
    }
    #pragma unroll
    for (int i=0;i<8;i++){
        float* cptr = g_C + (size_t)(m0 + tr*8 + i)*N2H + n0 + tc*8;
        F4U u0; u0.u[0]=acc2[i][0]; u0.u[1]=acc2[i][1];
        F4U u1; u1.u[0]=acc2[i][2]; u1.u[1]=acc2[i][3];
        *(float4*)(cptr)   = u0.f;
        *(float4*)(cptr+4) = u1.f;
    }
}

// ---------------------------------------------------------------------------
// Kernel 2: k-trace precompute.
// ---------------------------------------------------------------------------
__global__ __launch_bounds__(256) void trace_kernel(float* __restrict__ keys_out)
{
    int gid = blockIdx.x*blockDim.x + threadIdx.x;   // 0..32767
    int b = gid >> 9;
    int h = gid & 511;
    const float* c = g_C + (size_t)b*NS*N2H + h;      // ik column
    float* ko = keys_out + (size_t)b*NS*NHH + h;
    const float ALPHA = 0.9048374180359595f;
    float ks = 0.f;
    #pragma unroll 8
    for (int t=0;t<NS;t++){
        ks = fmaf(ks, ALPHA, __ldg(c + (size_t)t*N2H));
        ko[(size_t)t*NHH] = fast_tanh(ks);
    }
}

// ---------------------------------------------------------------------------
// Kernel 3: main recurrence. One warp owns 4 scaled mem rows (m''=mem/P) in
// registers. k_t staged through DOUBLE-BUFFERED SHARED MEMORY: one cooperative
// 2KB load per block per step (4x less L2 traffic than per-warp loads).
// Scalar chain packed f32x2, tanh via MUFU.TANH.
// Grid: (32 row-groups, 64 batches) x 128 threads (4 warps x 4 rows).
// ---------------------------------------------------------------------------
__global__ __launch_bounds__(128, 3) void recur_kernel(const float* __restrict__ keys,
                                                       float* __restrict__ mem_out,
                                                       float* __restrict__ vals_out)
{
    __shared__ float sk[2][NHH];

    const int b    = blockIdx.y;
    const int rg   = blockIdx.x;       // 0..31
    const int tid  = threadIdx.x;
    const int warp = tid >> 5;         // 0..3
    const int lane = tid & 31;
    const int row0 = rg*16 + warp*4;

    const float ALPHA = 0.9048374180359595f;   // exp(-1/10)
    const float DEC   = 0.9512294245007140f;   // exp(-1/20)
    const float OMD   = 0.0487705754992860f;   // 1 - DEC
    const float LR    = 0.01f;

    u64 m[4][8], kt[8];
    #pragma unroll
    for (int r=0;r<4;r++)
        #pragma unroll
        for (int p=0;p<8;p++) m[r][p]=0ULL;
    #pragma unroll
    for (int p=0;p<8;p++) kt[p]=0ULL;

    // packed per-row scalar state: (row0,row1) and (row2,row3)
    u64 vs01=0ULL, vs23=0ULL, vt01=0ULL, vt23=0ULL;
    u64 P01 = pk2(1.f,1.f),        P23 = pk2(1.f,1.f);
    u64 Q01 = pk2(LR*OMD, LR*OMD), Q23 = Q01;

    const u64 ONE2   = pk2(1.f, 1.f);
    const u64 NEG2   = pk2(-1.f, -1.f);
    const u64 A2     = pk2(ALPHA, ALPHA);
    const u64 DEC2   = pk2(DEC, DEC);
    const u64 OMD2   = pk2(OMD, OMD);
    const u64 LR2    = pk2(LR, LR);
    const u64 K02    = pk2(0.2f, 0.2f);

    const float* kg   = keys + (size_t)b*NS*NHH;            // global keys, batch b
    const float4* ivb = (const float4*)(g_C + (size_t)b*NS*N2H + NHH + row0);
    float4*       vb  = (float4*)(vals_out + (size_t)b*NS*NHH + row0);

    // preload k_0 into sk[0] (cooperative: 128 threads x float4 = 512 floats)
    *(float4*)(&sk[0][tid*4]) = *(const float4*)(kg + tid*4);
    float4 ivf = __ldg(&ivb[0]);
    __syncthreads();

    for (int t=0;t<NS;t++){
        const int cur = t & 1;
        // issue next-step global loads early (k_{t+1} -> regs, iv_{t+1})
        float4 knext;
        if (t+1 < NS) knext = *(const float4*)(kg + (size_t)(t+1)*NHH + tid*4);
        float4 ivn = __ldg(&ivb[(size_t)((t+1<NS)?(t+1):t)*(N2H/4)]);

        // read k_t from smem (conflict-free float4)
        u64 kp[8];
        #pragma unroll
        for (int c=0;c<4;c++){
            F4U kv; kv.f = *(const float4*)(&sk[cur][c*128 + lane*4]);
            kp[2*c] = kv.u[0]; kp[2*c+1] = kv.u[1];
        }
        u64 iv01 = pk2(ivf.x, ivf.y);
        u64 iv23 = pk2(ivf.z, ivf.w);

        // dots with current (scaled) mem — two accumulation trees per row
        u64 a[4];
        #pragma unroll
        for (int r=0;r<4;r++){
            u64 s0=0ULL, s1=0ULL;
            #pragma unroll
            for (int p=0;p<8;p+=2){
                s0 = fma2(m[r][p],   kp[p],   s0);
                s1 = fma2(m[r][p+1], kp[p+1], s1);
            }
            a[r] = add2(s0, s1);
        }

        // kt' update (independent of reduce -> overlaps shfl latency)
        #pragma unroll
        for (int p=0;p<8;p++) kt[p] = fma2(kt[p], DEC2, kp[p]);

        // horizontal + butterfly allreduce (two packed chains)
        float x,y;
        up2(a[0],x,y); float h0 = x+y;
        up2(a[1],x,y); float h1 = x+y;
        up2(a[2],x,y); float h2 = x+y;
        up2(a[3],x,y); float h3 = x+y;
        u64 r01 = pk2(h0,h1), r23 = pk2(h2,h3);
        #pragma unroll
        for (int o=16;o;o>>=1){
            r01 = add2(r01, __shfl_xor_sync(0xffffffffu, r01, o));
            r23 = add2(r23, __shfl_xor_sync(0xffffffffu, r23, o));
        }

        // packed scalar chains (warp-uniform)
        u64 d01 = mul2(r01, P01);
        u64 d23 = mul2(r23, P23);
        vs01 = fma2(vs01, A2, fma2(K02, d01, iv01));
        vs23 = fma2(vs23, A2, fma2(K02, d23, iv23));
        float v0,v1,v2,v3;
        { float s0,s1; up2(vs01,s0,s1); v0=tanh_approx(s0); v1=tanh_approx(s1); }
        { float s2,s3; up2(vs23,s2,s3); v2=tanh_approx(s2); v3=tanh_approx(s3); }
        u64 v01 = pk2(v0,v1), v23 = pk2(v2,v3);
        vt01 = fma2(v01, OMD2, mul2(vt01, DEC2));
        vt23 = fma2(v23, OMD2, mul2(vt23, DEC2));
        u64 e01 = mul2(mul2(vt01, vt01), LR2);
        u64 e23 = mul2(mul2(vt23, vt23), LR2);
        P01 = mul2(P01, fma2(e01, NEG2, ONE2));
        P23 = mul2(P23, fma2(e23, NEG2, ONE2));
        // 1/(1-e) ~= 1+e+e^2+e^3  (err ~ e^4 <= 1e-8)
        Q01 = mul2(Q01, fma2(e01, fma2(e01, add2(ONE2, e01), ONE2), ONE2));
        Q23 = mul2(Q23, fma2(e23, fma2(e23, add2(ONE2, e23), ONE2), ONE2));
        u64 w01 = mul2(Q01, vt01);
        u64 w23 = mul2(Q23, vt23);

        if (lane == 0)
            vb[(size_t)t*(NHH/4)] = make_float4(v0, v1, v2, v3);

        // scaled mem update: m''_r += kt' * w_r   (1 fma2 per element-pair)
        float w0,w1,w2,w3;
        up2(w01,w0,w1); up2(w23,w2,w3);
        u64 wp0=pk2(w0,w0), wp1=pk2(w1,w1), wp2=pk2(w2,w2), wp3=pk2(w3,w3);
        #pragma unroll
        for (int p=0;p<8;p++){
            m[0][p] = fma2(kt[p], wp0, m[0][p]);
            m[1][p] = fma2(kt[p], wp1, m[1][p]);
            m[2][p] = fma2(kt[p], wp2, m[2][p]);
            m[3][p] = fma2(kt[p], wp3, m[3][p]);
        }

        // stage k_{t+1} into the other smem buffer, then one sync per step
        if (t+1 < NS)
            *(float4*)(&sk[cur^1][tid*4]) = knext;
        ivf = ivn;
        __syncthreads();
    }

    // write final mem rows: mem = P_r * m''_r
    float Pf[4];
    up2(P01, Pf[0], Pf[1]); up2(P23, Pf[2], Pf[3]);
    #pragma unroll
    for (int r=0;r<4;r++){
        u64 Pp = pk2(Pf[r], Pf[r]);
        float* mo = mem_out + ((size_t)b*NHH + row0 + r)*NHH + lane*4;
        #pragma unroll
        for (int c=0;c<4;c++){
            F4U u;
            u.u[0] = mul2(m[r][2*c],   Pp);
            u.u[1] = mul2(m[r][2*c+1], Pp);
            *(float4*)(mo + c*128) = u.f;
        }
    }
}

// ---------------------------------------------------------------------------
extern "C" void kernel_launch(void* const* d_in, const int* in_sizes, int n_in,
                              void* d_out, int out_size)
{
    const float* x = (const float*)d_in[0];   // [64,256,256]
    const float* W = (const float*)d_in[1];   // [1024,256]
    float* out = (float*)d_out;
    float* mem_out  = out;                                    // [64,512,512]
    float* keys_out = out + (size_t)NB*NHH*NHH;               // [64,256,512]
    float* vals_out = keys_out + (size_t)NB*NS*NHH;           // [64,256,512]

    dim3 g1(N2H/BN, NM/BM);                 // (8, 128)
    sgemm_kernel<<<g1, 256>>>(x, W);
    trace_kernel<<<(NB*NHH)/256, 256>>>(keys_out);
    recur_kernel<<<dim3(32, NB), 128>>>(keys_out, mem_out, vals_out);
}